// round 1
// baseline (speedup 1.0000x reference)
#include <cuda_runtime.h>

#define BATCH   4
#define T       2048
#define DMODEL  1024
#define NH      16
#define DK      64
#define BH      (BATCH*NH)          // 64
#define M_TOT   (BATCH*T)           // 8192
#define N_QKV   (3*DMODEL)          // 3072
#define OUT_ELEMS ((size_t)BATCH*T*DMODEL)            // 8388608
#define PROB_ELEMS ((size_t)BATCH*NH*T*T)             // 268435456

// Scratch for Q/K/V in [B*H, T, DK] layout (32 MB each; __device__ globals are legal scratch)
__device__ float g_q[(size_t)BH * T * DK];
__device__ float g_k[(size_t)BH * T * DK];
__device__ float g_v[(size_t)BH * T * DK];

// ---------------------------------------------------------------------------
// Kernel 1: QKV projection. X[8192,1024] x W[1024,3072] + b, scattered into
// g_q/g_k/g_v with [b*H+h, t, dk] layout. 128x128x8 tiles, 8x8 per thread.
// ---------------------------------------------------------------------------
__global__ __launch_bounds__(256) void qkv_gemm_kernel(const float* __restrict__ X,
                                                       const float* __restrict__ W,
                                                       const float* __restrict__ bias) {
    __shared__ float As[8][128];   // transposed A tile: As[k][m]
    __shared__ float Bs[8][128];

    const int bm = blockIdx.y * 128;
    const int bn = blockIdx.x * 128;
    const int tid = threadIdx.x;
    const int ty = tid >> 4;       // 0..15
    const int tx = tid & 15;       // 0..15

    float acc[8][8];
#pragma unroll
    for (int i = 0; i < 8; i++)
#pragma unroll
        for (int j = 0; j < 8; j++) acc[i][j] = 0.f;

    const int a_row = tid >> 1;          // 0..127
    const int a_col = (tid & 1) * 4;     // 0 or 4
    const int b_row = tid >> 5;          // 0..7
    const int b_col = (tid & 31) * 4;    // 0..124

    for (int k0 = 0; k0 < DMODEL; k0 += 8) {
        float4 av = *reinterpret_cast<const float4*>(
            &X[(size_t)(bm + a_row) * DMODEL + k0 + a_col]);
        float4 bv = *reinterpret_cast<const float4*>(
            &W[(size_t)(k0 + b_row) * N_QKV + bn + b_col]);
        As[a_col + 0][a_row] = av.x;
        As[a_col + 1][a_row] = av.y;
        As[a_col + 2][a_row] = av.z;
        As[a_col + 3][a_row] = av.w;
        *reinterpret_cast<float4*>(&Bs[b_row][b_col]) = bv;
        __syncthreads();

#pragma unroll
        for (int kk = 0; kk < 8; kk++) {
            float4 a0 = *reinterpret_cast<const float4*>(&As[kk][ty * 4]);
            float4 a1 = *reinterpret_cast<const float4*>(&As[kk][64 + ty * 4]);
            float4 b0 = *reinterpret_cast<const float4*>(&Bs[kk][tx * 4]);
            float4 b1 = *reinterpret_cast<const float4*>(&Bs[kk][64 + tx * 4]);
            float ar[8] = {a0.x, a0.y, a0.z, a0.w, a1.x, a1.y, a1.z, a1.w};
            float br[8] = {b0.x, b0.y, b0.z, b0.w, b1.x, b1.y, b1.z, b1.w};
#pragma unroll
            for (int i = 0; i < 8; i++)
#pragma unroll
                for (int j = 0; j < 8; j++)
                    acc[i][j] = fmaf(ar[i], br[j], acc[i][j]);
        }
        __syncthreads();
    }

    // Scatter writeout into Q/K/V [bh, t, dk]
#pragma unroll
    for (int i = 0; i < 8; i++) {
        int m = bm + ((i < 4) ? (ty * 4 + i) : (64 + ty * 4 + (i - 4)));
        int b = m / T;
        int t = m % T;
#pragma unroll
        for (int j = 0; j < 8; j++) {
            int n = bn + ((j < 4) ? (tx * 4 + j) : (64 + tx * 4 + (j - 4)));
            float val = acc[i][j] + bias[n];
            int which = n / DMODEL;          // 0=q 1=k 2=v
            int nn = n % DMODEL;
            int h = nn / DK;
            int dk = nn % DK;
            float* dst = (which == 0) ? g_q : (which == 1) ? g_k : g_v;
            dst[(((size_t)(b * NH + h)) * T + t) * DK + dk] = val;
        }
    }
}

// ---------------------------------------------------------------------------
// Kernel 2: fused causal attention. One block per (bh, 64-row q-tile).
// Pass 1: accumulate row max + sumexp over k-tiles (online).
// Pass 2: recompute scores, write normalized prob, accumulate O = P @ V.
// Upper-triangle prob tiles are zero-filled (d_out is poisoned).
// ---------------------------------------------------------------------------
#define SROW 65   // padded row stride in shared (bank-conflict avoidance)

__global__ __launch_bounds__(256) void attn_kernel(float* __restrict__ out,
                                                   float* __restrict__ prob,
                                                   int write_prob) {
    extern __shared__ float sm[];
    float* Qs   = sm;                    // 64 x SROW
    float* Ks   = Qs + 64 * SROW;
    float* Vs   = Ks + 64 * SROW;
    float* Ss   = Vs + 64 * SROW;
    float* mrow = Ss + 64 * SROW;        // 64
    float* lrow = mrow + 64;             // 64

    const int qt  = blockIdx.x;          // 0..31
    const int bh  = blockIdx.y;          // 0..63
    const int tid = threadIdx.x;
    const int ty  = tid >> 4;            // 0..15 -> rows ty*4..+3
    const int tx  = tid & 15;            // 0..15 -> cols tx*4..+3

    const float* Qg = g_q + (size_t)bh * T * DK;
    const float* Kg = g_k + (size_t)bh * T * DK;
    const float* Vg = g_v + (size_t)bh * T * DK;

    // Load Q tile, pre-scaled by 1/sqrt(64) = 0.125
#pragma unroll
    for (int i = 0; i < 4; i++) {
        int f = tid + 256 * i;           // float4 index in 64x64 tile
        int r = f >> 4;
        int c = (f & 15) * 4;
        float4 v = *reinterpret_cast<const float4*>(&Qg[(size_t)(qt * 64 + r) * DK + c]);
        Qs[r * SROW + c + 0] = v.x * 0.125f;
        Qs[r * SROW + c + 1] = v.y * 0.125f;
        Qs[r * SROW + c + 2] = v.z * 0.125f;
        Qs[r * SROW + c + 3] = v.w * 0.125f;
    }
    if (tid < 64) { mrow[tid] = -1e30f; lrow[tid] = 0.f; }
    __syncthreads();

    // -------------------- Pass 1: row max + sumexp --------------------
    for (int kt = 0; kt <= qt; kt++) {
#pragma unroll
        for (int i = 0; i < 4; i++) {
            int f = tid + 256 * i;
            int r = f >> 4;
            int c = (f & 15) * 4;
            float4 v = *reinterpret_cast<const float4*>(&Kg[(size_t)(kt * 64 + r) * DK + c]);
            Ks[r * SROW + c + 0] = v.x;
            Ks[r * SROW + c + 1] = v.y;
            Ks[r * SROW + c + 2] = v.z;
            Ks[r * SROW + c + 3] = v.w;
        }
        __syncthreads();

        float s[4][4];
#pragma unroll
        for (int i = 0; i < 4; i++)
#pragma unroll
            for (int j = 0; j < 4; j++) s[i][j] = 0.f;
#pragma unroll 8
        for (int d = 0; d < 64; d++) {
            float a[4], b[4];
#pragma unroll
            for (int i = 0; i < 4; i++) a[i] = Qs[(ty * 4 + i) * SROW + d];
#pragma unroll
            for (int j = 0; j < 4; j++) b[j] = Ks[(tx * 4 + j) * SROW + d];
#pragma unroll
            for (int i = 0; i < 4; i++)
#pragma unroll
                for (int j = 0; j < 4; j++) s[i][j] = fmaf(a[i], b[j], s[i][j]);
        }
#pragma unroll
        for (int i = 0; i < 4; i++) {
            int qg = qt * 64 + ty * 4 + i;
#pragma unroll
            for (int j = 0; j < 4; j++) {
                int kg = kt * 64 + tx * 4 + j;
                Ss[(ty * 4 + i) * SROW + tx * 4 + j] = (kg <= qg) ? s[i][j] : -1e30f;
            }
        }
        __syncthreads();

        if (tid < 64) {
            const float* row = Ss + tid * SROW;
            float mx = mrow[tid];
#pragma unroll 8
            for (int c = 0; c < 64; c++) mx = fmaxf(mx, row[c]);
            float sum = 0.f;
#pragma unroll 8
            for (int c = 0; c < 64; c++) sum += __expf(row[c] - mx);
            lrow[tid] = lrow[tid] * __expf(mrow[tid] - mx) + sum;
            mrow[tid] = mx;
        }
        __syncthreads();
    }

    if (tid < 64) lrow[tid] = 1.f / lrow[tid];
    __syncthreads();

    // -------------------- Pass 2: prob write + O = P@V --------------------
    float o[4][4];
#pragma unroll
    for (int i = 0; i < 4; i++)
#pragma unroll
        for (int j = 0; j < 4; j++) o[i][j] = 0.f;

    for (int kt = 0; kt <= qt; kt++) {
#pragma unroll
        for (int i = 0; i < 4; i++) {
            int f = tid + 256 * i;
            int r = f >> 4;
            int c = (f & 15) * 4;
            float4 kv = *reinterpret_cast<const float4*>(&Kg[(size_t)(kt * 64 + r) * DK + c]);
            float4 vv = *reinterpret_cast<const float4*>(&Vg[(size_t)(kt * 64 + r) * DK + c]);
            Ks[r * SROW + c + 0] = kv.x;
            Ks[r * SROW + c + 1] = kv.y;
            Ks[r * SROW + c + 2] = kv.z;
            Ks[r * SROW + c + 3] = kv.w;
            Vs[r * SROW + c + 0] = vv.x;
            Vs[r * SROW + c + 1] = vv.y;
            Vs[r * SROW + c + 2] = vv.z;
            Vs[r * SROW + c + 3] = vv.w;
        }
        __syncthreads();

        float s[4][4];
#pragma unroll
        for (int i = 0; i < 4; i++)
#pragma unroll
            for (int j = 0; j < 4; j++) s[i][j] = 0.f;
#pragma unroll 8
        for (int d = 0; d < 64; d++) {
            float a[4], b[4];
#pragma unroll
            for (int i = 0; i < 4; i++) a[i] = Qs[(ty * 4 + i) * SROW + d];
#pragma unroll
            for (int j = 0; j < 4; j++) b[j] = Ks[(tx * 4 + j) * SROW + d];
#pragma unroll
            for (int i = 0; i < 4; i++)
#pragma unroll
                for (int j = 0; j < 4; j++) s[i][j] = fmaf(a[i], b[j], s[i][j]);
        }
#pragma unroll
        for (int i = 0; i < 4; i++) {
            int qg = qt * 64 + ty * 4 + i;
            float mi = mrow[ty * 4 + i];
            float li = lrow[ty * 4 + i];
#pragma unroll
            for (int j = 0; j < 4; j++) {
                int kg = kt * 64 + tx * 4 + j;
                float p = (kg <= qg) ? __expf(s[i][j] - mi) * li : 0.f;
                Ss[(ty * 4 + i) * SROW + tx * 4 + j] = p;
            }
        }
        __syncthreads();

        if (write_prob) {
#pragma unroll
            for (int i2 = 0; i2 < 4; i2++) {
                int f = tid + 256 * i2;
                int r = f >> 4;
                int c = (f & 15) * 4;
                float4 pv;
                pv.x = Ss[r * SROW + c + 0];
                pv.y = Ss[r * SROW + c + 1];
                pv.z = Ss[r * SROW + c + 2];
                pv.w = Ss[r * SROW + c + 3];
                *reinterpret_cast<float4*>(
                    &prob[(((size_t)bh * T + qt * 64 + r) * T) + kt * 64 + c]) = pv;
            }
        }

#pragma unroll 8
        for (int kk = 0; kk < 64; kk++) {
            float p4[4], v4[4];
#pragma unroll
            for (int i = 0; i < 4; i++) p4[i] = Ss[(ty * 4 + i) * SROW + kk];
#pragma unroll
            for (int j = 0; j < 4; j++) v4[j] = Vs[kk * SROW + tx * 4 + j];
#pragma unroll
            for (int i = 0; i < 4; i++)
#pragma unroll
                for (int j = 0; j < 4; j++) o[i][j] = fmaf(p4[i], v4[j], o[i][j]);
        }
        __syncthreads();
    }

    // Zero-fill the never-visited upper-triangle tiles (buffer is poisoned)
    if (write_prob) {
        for (int kt = qt + 1; kt < T / 64; kt++) {
#pragma unroll
            for (int i2 = 0; i2 < 4; i2++) {
                int f = tid + 256 * i2;
                int r = f >> 4;
                int c = (f & 15) * 4;
                *reinterpret_cast<float4*>(
                    &prob[(((size_t)bh * T + qt * 64 + r) * T) + kt * 64 + c]) =
                    make_float4(0.f, 0.f, 0.f, 0.f);
            }
        }
    }

    // Writeout: out[b, t, h*64 + d]
    const int b = bh / NH;
    const int h = bh % NH;
#pragma unroll
    for (int i = 0; i < 4; i++) {
        int t = qt * 64 + ty * 4 + i;
        float4 ov = make_float4(o[i][0], o[i][1], o[i][2], o[i][3]);
        *reinterpret_cast<float4*>(
            &out[((size_t)(b * T + t)) * DMODEL + h * DK + tx * 4]) = ov;
    }
}

// ---------------------------------------------------------------------------
extern "C" void kernel_launch(void* const* d_in, const int* in_sizes, int n_in,
                              void* d_out, int out_size) {
    const float* x    = (const float*)d_in[0];
    const float* Wqkv = (const float*)d_in[1];
    const float* bqkv = (const float*)d_in[2];
    // d_in[3] (W_o), d_in[4] (b_o) unused per reference semantics.

    float* out  = (float*)d_out;
    float* prob = out + OUT_ELEMS;
    int write_prob = ((size_t)out_size >= OUT_ELEMS + PROB_ELEMS) ? 1 : 0;

    dim3 g1(N_QKV / 128, M_TOT / 128);
    qkv_gemm_kernel<<<g1, 256>>>(x, Wqkv, bqkv);

    const int SMEM = (4 * 64 * SROW + 128) * (int)sizeof(float);  // 67072 B
    cudaFuncSetAttribute(attn_kernel, cudaFuncAttributeMaxDynamicSharedMemorySize, SMEM);
    dim3 g2(T / 64, BH);
    attn_kernel<<<g2, 256, SMEM>>>(out, prob, write_prob);
}